// round 6
// baseline (speedup 1.0000x reference)
#include <cuda_runtime.h>
#include <cuda_fp16.h>
#include <cstdint>

#define D       64
#define KCB     1024
#define TLEN    8192
#define MTOK    128       // tokens per CTA
#define THREADS 256       // 8 warps, 16 tokens per warp
#define CHUNK   256       // codes per chunk
#define NCHUNK  4
#define TAU     0.09f
#define NTOKMAX 131072

// ---- dynamic smem layout (bytes) ----
#define OFF_XH   0                 // 128 tokens x 128B rows (fp16), SW128
#define OFF_B    16384             // 2 bufs x 32KB (256 codes x 128B fp16)
#define OFF_H    81920             // float[1024]
#define OFF_IDX  86016             // int[128]
#define SMEM_TOTAL 86528

// ---- global scratch (no allocs allowed in kernel_launch) ----
__device__ __align__(16) __half g_cbH[KCB * D];   // fp16 codebook [k][d]
__device__ float g_h[KCB];                         // 0.5*||e_k||^2 (fp32)
__device__ int   g_flag[NTOKMAX];

// ============================ PTX helpers ===================================
__device__ __forceinline__ uint32_t smem_u32(const void* p) {
    uint32_t a;
    asm("{ .reg .u64 t; cvta.to.shared.u64 t, %1; cvt.u32.u64 %0, t; }"
        : "=r"(a) : "l"(p));
    return a;
}
__device__ __forceinline__ void ldsm_x4(uint32_t r[4], uint32_t addr) {
    asm volatile("ldmatrix.sync.aligned.m8n8.x4.shared.b16 {%0,%1,%2,%3}, [%4];"
                 : "=r"(r[0]), "=r"(r[1]), "=r"(r[2]), "=r"(r[3]) : "r"(addr));
}
__device__ __forceinline__ void mma_f16(float c[4], const uint32_t a[4],
                                        uint32_t b0, uint32_t b1) {
    asm volatile(
        "mma.sync.aligned.m16n8k16.row.col.f32.f16.f16.f32 "
        "{%0,%1,%2,%3}, {%4,%5,%6,%7}, {%8,%9}, {%0,%1,%2,%3};"
        : "+f"(c[0]), "+f"(c[1]), "+f"(c[2]), "+f"(c[3])
        : "r"(a[0]), "r"(a[1]), "r"(a[2]), "r"(a[3]), "r"(b0), "r"(b1));
}
__device__ __forceinline__ void cp16(uint32_t dst, const void* src) {
    asm volatile("cp.async.ca.shared.global [%0], [%1], 16;"
                 :: "r"(dst), "l"(src) : "memory");
}
__device__ __forceinline__ void cp_commit() {
    asm volatile("cp.async.commit_group;" ::: "memory");
}
template <int N> __device__ __forceinline__ void cp_wait() {
    asm volatile("cp.async.wait_group %0;" :: "n"(N) : "memory");
}
__device__ __forceinline__ uint32_t sw128(uint32_t off) {
    return off ^ ((off >> 3) & 0x70);
}

// ============================ prep ==========================================
// Warp per 4 codes: coalesced row loads, fp16 convert, shfl-reduced h[k].
// (Measured 4.7us in R5.)
__global__ void __launch_bounds__(256) vq_prep(const float* __restrict__ cb) {
    const int lane = threadIdx.x & 31, w = threadIdx.x >> 5;
    const int wglobal = blockIdx.x * 8 + w;        // 256 warps
#pragma unroll
    for (int i = 0; i < 4; i++) {
        int k = wglobal * 4 + i;                   // 1024 codes
        float f0 = cb[k * D + lane];
        float f1 = cb[k * D + lane + 32];
        g_cbH[k * D + lane]      = __float2half(f0);
        g_cbH[k * D + lane + 32] = __float2half(f1);
        float s = fmaf(f0, f0, f1 * f1);
#pragma unroll
        for (int off = 16; off; off >>= 1)
            s += __shfl_xor_sync(0xffffffffu, s, off);
        if (lane == 0) g_h[k] = 0.5f * s;
    }
}

// ============================ main ==========================================
__device__ __forceinline__ void issueB(uint32_t smbase, int buf, int chunk, int tid) {
    uint32_t dst = smbase + OFF_B + buf * 32768;
    const char* src = reinterpret_cast<const char*>(g_cbH) + (size_t)chunk * CHUNK * D * 2;
#pragma unroll
    for (int i = tid; i < 2048; i += THREADS) {
        int code = i >> 3, q = i & 7;
        uint32_t sw = sw128((uint32_t)(code * 128 + q * 16));
        cp16(dst + sw, src + i * 16);
    }
}

__device__ __forceinline__ void upd(float& b, float& s, int& bi, float v, int k) {
    s = fmaxf(s, fminf(v, b));      // running second-best
    if (v > b) { b = v; bi = k; }   // strict > keeps first occurrence
}

__global__ void __launch_bounds__(THREADS, 1)
vq_mma(const float* __restrict__ xin, const float* __restrict__ cb,
       float* __restrict__ out, float* __restrict__ outidx) {
    extern __shared__ __align__(1024) char sm[];
    const uint32_t smbase = smem_u32(sm);
    const int tid  = threadIdx.x;
    const int lane = tid & 31, warp = tid >> 5;

    const int n0 = blockIdx.x * MTOK;
    const int b  = n0 >> 13;            // / TLEN
    const int t0 = n0 & (TLEN - 1);

    // Kick off codebook chunks 0,1 so they overlap X staging.
    issueB(smbase, 0, 0, tid); cp_commit();
    issueB(smbase, 1, 1, tid); cp_commit();

    // Stage X as fp16, SW128 rows of 128B (row = token).
    const float* xbase = xin + (size_t)b * D * TLEN + t0;
    for (int i = tid; i < MTOK * D; i += THREADS) {
        int d = i >> 7, m = i & 127;    // coalesced over m
        float v = xbase[(size_t)d * TLEN + m];
        uint32_t sw = sw128((uint32_t)(m * 128 + d * 2));
        *reinterpret_cast<__half*>(sm + OFF_XH + sw) = __float2half(v);
    }
    float* sH = reinterpret_cast<float*>(sm + OFF_H);
    for (int i = tid; i < KCB; i += THREADS) sH[i] = g_h[i];
    __syncthreads();    // X + h visible to all warps

    // A fragments (held in registers for the whole kernel).
    uint32_t aX[4][4];
    {
        int arow = warp * 16 + (lane & 15);
        int adim = (lane >> 4) * 16;            // byte offset of 8-dim half
#pragma unroll
        for (int s = 0; s < 4; s++) {
            uint32_t sw = sw128((uint32_t)(arow * 128 + s * 32 + adim));
            ldsm_x4(aX[s], smbase + OFF_XH + sw);
        }
    }

    // B-fragment addressing (16 codes x 16 dims per ldmatrix.x4).
    const uint32_t browoff = (uint32_t)(((lane & 7) + ((lane >> 4) << 3)) * 128);
    const uint32_t bxor = (uint32_t)((lane & 7) << 4);
    uint32_t bdim[4];
#pragma unroll
    for (int s = 0; s < 4; s++)
        bdim[s] = ((uint32_t)(s * 32 + ((lane >> 3) & 1) * 16)) ^ bxor;

    float best[2] = {-3.4e38f, -3.4e38f}, sec[2] = {-3.4e38f, -3.4e38f};
    int   bidx[2] = {0, 0};
    const int hcol = (lane & 3) * 2;

    for (int c = 0; c < NCHUNK; c++) {
        if (c == NCHUNK - 1) cp_wait<0>(); else cp_wait<1>();
        __syncthreads();                 // buf (c&1) ready for everyone
        const uint32_t buf = smbase + OFF_B + (c & 1) * 32768;

#pragma unroll 4
        for (int ns = 0; ns < CHUNK / 16; ns++) {
            const uint32_t ro = browoff + (uint32_t)(ns * 16 * 128);
            float a0[4] = {0, 0, 0, 0};          // cols kb..kb+7  (rows r, r+8)
            float a1[4] = {0, 0, 0, 0};          // cols kb+8..kb+15
#pragma unroll
            for (int s = 0; s < 4; s++) {
                uint32_t rh[4];
                ldsm_x4(rh, buf + ro + bdim[s]);
                mma_f16(a0, aX[s], rh[0], rh[1]);
                mma_f16(a1, aX[s], rh[2], rh[3]);
            }
            const int kb = c * CHUNK + ns * 16;
            float2 h0 = *reinterpret_cast<const float2*>(&sH[kb + hcol]);
            float2 h1 = *reinterpret_cast<const float2*>(&sH[kb + 8 + hcol]);
            // slot 0 = token row r (c0,c1); slot 1 = row r+8 (c2,c3).
            upd(best[0], sec[0], bidx[0], a0[0] - h0.x, kb + hcol);
            upd(best[0], sec[0], bidx[0], a0[1] - h0.y, kb + hcol + 1);
            upd(best[0], sec[0], bidx[0], a1[0] - h1.x, kb + 8 + hcol);
            upd(best[0], sec[0], bidx[0], a1[1] - h1.y, kb + 8 + hcol + 1);
            upd(best[1], sec[1], bidx[1], a0[2] - h0.x, kb + hcol);
            upd(best[1], sec[1], bidx[1], a0[3] - h0.y, kb + hcol + 1);
            upd(best[1], sec[1], bidx[1], a1[2] - h1.x, kb + 8 + hcol);
            upd(best[1], sec[1], bidx[1], a1[3] - h1.y, kb + 8 + hcol + 1);
        }
        __syncthreads();                 // everyone done reading buf (c&1)
        if (c + 2 < NCHUNK) { issueB(smbase, c & 1, c + 2, tid); cp_commit(); }
    }

    // Reduce across the 4 lanes (lane&3) sharing each token row.
    int* sIdx = reinterpret_cast<int*>(sm + OFF_IDX);
#pragma unroll
    for (int slot = 0; slot < 2; slot++) {
        float bv = best[slot], sv = sec[slot];
        int bi = bidx[slot];
#pragma unroll
        for (int off = 1; off <= 2; off <<= 1) {
            float ob = __shfl_xor_sync(0xffffffffu, bv, off);
            float os = __shfl_xor_sync(0xffffffffu, sv, off);
            int   oi = __shfl_xor_sync(0xffffffffu, bi, off);
            sv = fmaxf(fmaxf(sv, os), fminf(bv, ob));
            bool t = (ob > bv) || (ob == bv && oi < bi);  // tie -> smaller idx
            bv = t ? ob : bv;
            bi = t ? oi : bi;
        }
        if ((lane & 3) == 0) {
            int m = warp * 16 + (lane >> 2) + slot * 8;
            sIdx[m] = bi;
            g_flag[n0 + m] = (bv - sv < TAU) ? 1 : 0;
            outidx[n0 + m] = (float)bi;
        }
    }
    __syncthreads();

    // Gather winning codebook rows; coalesced over tokens per dim.
    float* obase = out + (size_t)b * D * TLEN + t0;
    for (int i = tid; i < MTOK * D; i += THREADS) {
        int d = i >> 7, mm = i & 127;
        obase[(size_t)d * TLEN + mm] = cb[sIdx[mm] * D + d];
    }
}

// ============================ exact refine ==================================
// One warp per flagged token; exact fp32 fmaf chain (matched reference R1/R2).
__global__ void __launch_bounds__(256) vq_refine(const float* __restrict__ xin,
                                                 const float* __restrict__ cb,
                                                 float* __restrict__ out,
                                                 float* __restrict__ outidx,
                                                 int Ntok) {
    __shared__ float sx[8][D];
    const int wid = threadIdx.x >> 5, lid = threadIdx.x & 31;
    const int n = blockIdx.x * 8 + wid;
    if (n >= Ntok) return;
    if (g_flag[n] == 0) return;

    const int b = n / TLEN, t = n % TLEN;
    const float* xp = xin + (size_t)b * D * TLEN + t;
    sx[wid][lid]      = xp[(size_t)lid * TLEN];
    sx[wid][lid + 32] = xp[(size_t)(lid + 32) * TLEN];
    __syncwarp();

    float best = -3.4e38f;
    int   bi = 0;
    for (int kk = 0; kk < KCB / 32; kk++) {
        int k = kk * 32 + lid;
        const float4* row = reinterpret_cast<const float4*>(cb + (size_t)k * D);
        float dot = 0.0f;
#pragma unroll
        for (int q = 0; q < 16; q++) {
            float4 e = row[q];
            dot = fmaf(sx[wid][4 * q + 0], e.x, dot);
            dot = fmaf(sx[wid][4 * q + 1], e.y, dot);
            dot = fmaf(sx[wid][4 * q + 2], e.z, dot);
            dot = fmaf(sx[wid][4 * q + 3], e.w, dot);
        }
        float s = dot - g_h[k];
        if (s > best) { best = s; bi = k; }
    }
#pragma unroll
    for (int off = 16; off; off >>= 1) {   // tie -> smaller index
        float ov = __shfl_xor_sync(0xffffffffu, best, off);
        int   oi = __shfl_xor_sync(0xffffffffu, bi, off);
        if (ov > best || (ov == best && oi < bi)) { best = ov; bi = oi; }
    }
    bi = __shfl_sync(0xffffffffu, bi, 0);

    float* op = out + (size_t)b * D * TLEN + t;
    op[(size_t)lid * TLEN]        = cb[bi * D + lid];
    op[(size_t)(lid + 32) * TLEN] = cb[bi * D + lid + 32];
    if (lid == 0) outidx[n] = (float)bi;
}

// ============================ launch ========================================
extern "C" void kernel_launch(void* const* d_in, const int* in_sizes, int n_in,
                              void* d_out, int out_size) {
    const float* x  = (const float*)d_in[0];   // (16, 64, 8192)
    const float* cb = (const float*)d_in[1];   // (1024, 64)
    float* out = (float*)d_out;

    const int N = in_sizes[0] / D;
    float* oidx = out + (size_t)N * D;

    cudaFuncSetAttribute(vq_mma, cudaFuncAttributeMaxDynamicSharedMemorySize,
                         SMEM_TOTAL);

    vq_prep<<<32, 256>>>(cb);
    vq_mma<<<N / MTOK, THREADS, SMEM_TOTAL>>>(x, cb, out, oidx);
    vq_refine<<<N / 8, 256>>>(x, cb, out, oidx, N);
}

// round 7
// speedup vs baseline: 1.8939x; 1.8939x over previous
#include <cuda_runtime.h>
#include <cuda_bf16.h>
#include <cstdint>

#define D       64
#define KCB     1024
#define TLEN    8192
#define MTOK    128       // tokens per CTA
#define THREADS 256       // 8 warps, 16 tokens per warp
#define CHUNK   256       // codes per chunk
#define NCHUNK  4
#define TAU     3e-3f
#define NTOKMAX 131072

// ---- dynamic smem layout (bytes) ----
#define OFF_XHI  0                 // 128 tokens x 128B rows (bf16 hi), SW128
#define OFF_XLO  16384
#define OFF_B    32768             // 2 bufs x (hi 32KB + lo 32KB)
#define OFF_H    163840            // float[1024]
#define OFF_IDX  167936            // int[128]
#define SMEM_TOTAL 168448

// ---- global scratch (no allocs allowed in kernel_launch) ----
__device__ __align__(16) __nv_bfloat16 g_cbHi[KCB * D];  // [k][d]
__device__ __align__(16) __nv_bfloat16 g_cbLo[KCB * D];
__device__ float g_h[KCB];
__device__ int   g_flag[NTOKMAX];

// ============================ PTX helpers ===================================
__device__ __forceinline__ uint32_t smem_u32(const void* p) {
    uint32_t a;
    asm("{ .reg .u64 t; cvta.to.shared.u64 t, %1; cvt.u32.u64 %0, t; }"
        : "=r"(a) : "l"(p));
    return a;
}
__device__ __forceinline__ void ldsm_x4(uint32_t r[4], uint32_t addr) {
    asm volatile("ldmatrix.sync.aligned.m8n8.x4.shared.b16 {%0,%1,%2,%3}, [%4];"
                 : "=r"(r[0]), "=r"(r[1]), "=r"(r[2]), "=r"(r[3]) : "r"(addr));
}
__device__ __forceinline__ void mma_bf16(float c[4], const uint32_t a[4],
                                         uint32_t b0, uint32_t b1) {
    asm volatile(
        "mma.sync.aligned.m16n8k16.row.col.f32.bf16.bf16.f32 "
        "{%0,%1,%2,%3}, {%4,%5,%6,%7}, {%8,%9}, {%0,%1,%2,%3};"
        : "+f"(c[0]), "+f"(c[1]), "+f"(c[2]), "+f"(c[3])
        : "r"(a[0]), "r"(a[1]), "r"(a[2]), "r"(a[3]), "r"(b0), "r"(b1));
}
__device__ __forceinline__ void cp16(uint32_t dst, const void* src) {
    asm volatile("cp.async.ca.shared.global [%0], [%1], 16;"
                 :: "r"(dst), "l"(src) : "memory");
}
__device__ __forceinline__ void cp_commit() {
    asm volatile("cp.async.commit_group;" ::: "memory");
}
template <int N> __device__ __forceinline__ void cp_wait() {
    asm volatile("cp.async.wait_group %0;" :: "n"(N) : "memory");
}
__device__ __forceinline__ uint32_t sw128(uint32_t off) {
    return off ^ ((off >> 3) & 0x70);
}

// ============================ prep (fast) ===================================
// Warp per 4 codes: coalesced row loads, bf16 hi/lo split, shfl-reduced
// h[k] = 0.5*||e_k||^2. (This structure measured 4.6us in R5/R6.)
__global__ void __launch_bounds__(256) vq_prep(const float* __restrict__ cb) {
    const int lane = threadIdx.x & 31, w = threadIdx.x >> 5;
    const int wglobal = blockIdx.x * 8 + w;        // 256 warps
#pragma unroll
    for (int i = 0; i < 4; i++) {
        int k = wglobal * 4 + i;                   // 1024 codes
        float f0 = cb[k * D + lane];
        float f1 = cb[k * D + lane + 32];
        __nv_bfloat16 h0 = __float2bfloat16(f0);
        __nv_bfloat16 h1 = __float2bfloat16(f1);
        g_cbHi[k * D + lane]      = h0;
        g_cbHi[k * D + lane + 32] = h1;
        g_cbLo[k * D + lane]      = __float2bfloat16(f0 - __bfloat162float(h0));
        g_cbLo[k * D + lane + 32] = __float2bfloat16(f1 - __bfloat162float(h1));
        float s = fmaf(f0, f0, f1 * f1);
#pragma unroll
        for (int off = 16; off; off >>= 1)
            s += __shfl_xor_sync(0xffffffffu, s, off);
        if (lane == 0) g_h[k] = 0.5f * s;
    }
}

// ============================ main ==========================================
__device__ __forceinline__ void issueB(uint32_t smbase, int buf, int chunk, int tid) {
    // 256 codes x 128B (hi) and (lo), SW128-swizzled rows, via cp.async 16B.
    uint32_t dH = smbase + OFF_B + buf * 65536;
    uint32_t dL = dH + 32768;
    const char* sH = reinterpret_cast<const char*>(g_cbHi) + (size_t)chunk * CHUNK * D * 2;
    const char* sL = reinterpret_cast<const char*>(g_cbLo) + (size_t)chunk * CHUNK * D * 2;
#pragma unroll
    for (int i = tid; i < 2048; i += THREADS) {
        int code = i >> 3, q = i & 7;
        uint32_t sw = sw128((uint32_t)(code * 128 + q * 16));
        cp16(dH + sw, sH + i * 16);
        cp16(dL + sw, sL + i * 16);
    }
}

__device__ __forceinline__ void upd(float& b, float& s, int& bi, float v, int k) {
    s = fmaxf(s, fminf(v, b));      // running second-best
    if (v > b) { b = v; bi = k; }   // strict > keeps first occurrence
}

__global__ void __launch_bounds__(THREADS, 1)
vq_mma(const float* __restrict__ xin, const float* __restrict__ cb,
       float* __restrict__ out, float* __restrict__ outidx) {
    extern __shared__ __align__(1024) char sm[];
    const uint32_t smbase = smem_u32(sm);
    const int tid  = threadIdx.x;
    const int lane = tid & 31, warp = tid >> 5;

    const int n0 = blockIdx.x * MTOK;
    const int b  = n0 >> 13;            // / TLEN
    const int t0 = n0 & (TLEN - 1);

    // Kick off codebook chunks 0,1 first so they overlap X staging.
    issueB(smbase, 0, 0, tid); cp_commit();
    issueB(smbase, 1, 1, tid); cp_commit();

    // Stage X as bf16 hi/lo, SW128 rows of 128B (row = token).
    const float* xbase = xin + (size_t)b * D * TLEN + t0;
    for (int i = tid; i < MTOK * D; i += THREADS) {
        int d = i >> 7, m = i & 127;    // coalesced over m
        float v = xbase[(size_t)d * TLEN + m];
        __nv_bfloat16 hi = __float2bfloat16(v);
        __nv_bfloat16 lo = __float2bfloat16(v - __bfloat162float(hi));
        uint32_t sw = sw128((uint32_t)(m * 128 + d * 2));
        *reinterpret_cast<__nv_bfloat16*>(sm + OFF_XHI + sw) = hi;
        *reinterpret_cast<__nv_bfloat16*>(sm + OFF_XLO + sw) = lo;
    }
    float* sH = reinterpret_cast<float*>(sm + OFF_H);
    for (int i = tid; i < KCB; i += THREADS) sH[i] = g_h[i];
    __syncthreads();    // X + h visible to all warps

    // A fragments (held in registers for the whole kernel).
    // ldmatrix.x4: row = lane&15 (token in warp tile), dim half = lane>>4.
    uint32_t aHi[4][4], aLo[4][4];
    {
        int arow = warp * 16 + (lane & 15);
        int adim = (lane >> 4) * 16;            // byte offset of 8-dim half
#pragma unroll
        for (int s = 0; s < 4; s++) {
            uint32_t off = (uint32_t)(arow * 128 + s * 32 + adim);
            uint32_t sw = sw128(off);
            ldsm_x4(aHi[s], smbase + OFF_XHI + sw);
            ldsm_x4(aLo[s], smbase + OFF_XLO + sw);
        }
    }

    // B-fragment per-thread addressing (16 codes x 16 dims per ldmatrix.x4):
    // code_local = (lane&7) + ((lane>>4)<<3), dim half = (lane>>3)&1.
    const uint32_t browoff = (uint32_t)(((lane & 7) + ((lane >> 4) << 3)) * 128);
    const uint32_t bxor = (uint32_t)((lane & 7) << 4);
    uint32_t bdim[4];
#pragma unroll
    for (int s = 0; s < 4; s++)
        bdim[s] = ((uint32_t)(s * 32 + ((lane >> 3) & 1) * 16)) ^ bxor;

    float best[2] = {-3.4e38f, -3.4e38f}, sec[2] = {-3.4e38f, -3.4e38f};
    int   bidx[2] = {0, 0};
    const int hcol = (lane & 3) * 2;

    for (int c = 0; c < NCHUNK; c++) {
        if (c == NCHUNK - 1) cp_wait<0>(); else cp_wait<1>();
        __syncthreads();                 // buf (c&1) ready for everyone
        const uint32_t bufHi = smbase + OFF_B + (c & 1) * 65536;
        const uint32_t bufLo = bufHi + 32768;

#pragma unroll 4
        for (int ns = 0; ns < CHUNK / 16; ns++) {
            const uint32_t ro = browoff + (uint32_t)(ns * 16 * 128);
            float a0h[4] = {0, 0, 0, 0}, a0x[4] = {0, 0, 0, 0};  // ntile 0
            float a1h[4] = {0, 0, 0, 0}, a1x[4] = {0, 0, 0, 0};  // ntile 1
#pragma unroll
            for (int s = 0; s < 4; s++) {
                uint32_t rh[4], rl[4];
                ldsm_x4(rh, bufHi + ro + bdim[s]);
                ldsm_x4(rl, bufLo + ro + bdim[s]);
                mma_bf16(a0h, aHi[s], rh[0], rh[1]);   // hi*hi
                mma_bf16(a1h, aHi[s], rh[2], rh[3]);
                mma_bf16(a0x, aHi[s], rl[0], rl[1]);   // hi*lo
                mma_bf16(a1x, aHi[s], rl[2], rl[3]);
                mma_bf16(a0x, aLo[s], rh[0], rh[1]);   // lo*hi
                mma_bf16(a1x, aLo[s], rh[2], rh[3]);
            }
            const int kb = c * CHUNK + ns * 16;
            float2 h0 = *reinterpret_cast<const float2*>(&sH[kb + hcol]);
            float2 h1 = *reinterpret_cast<const float2*>(&sH[kb + 8 + hcol]);
            // slot 0 = token row r (c0,c1); slot 1 = row r+8 (c2,c3).
            upd(best[0], sec[0], bidx[0], (a0h[0] + a0x[0]) - h0.x, kb + hcol);
            upd(best[0], sec[0], bidx[0], (a0h[1] + a0x[1]) - h0.y, kb + hcol + 1);
            upd(best[0], sec[0], bidx[0], (a1h[0] + a1x[0]) - h1.x, kb + 8 + hcol);
            upd(best[0], sec[0], bidx[0], (a1h[1] + a1x[1]) - h1.y, kb + 8 + hcol + 1);
            upd(best[1], sec[1], bidx[1], (a0h[2] + a0x[2]) - h0.x, kb + hcol);
            upd(best[1], sec[1], bidx[1], (a0h[3] + a0x[3]) - h0.y, kb + hcol + 1);
            upd(best[1], sec[1], bidx[1], (a1h[2] + a1x[2]) - h1.x, kb + 8 + hcol);
            upd(best[1], sec[1], bidx[1], (a1h[3] + a1x[3]) - h1.y, kb + 8 + hcol + 1);
        }
        __syncthreads();                 // everyone done reading buf (c&1)
        if (c + 2 < NCHUNK) { issueB(smbase, c & 1, c + 2, tid); cp_commit(); }
    }

    // Reduce across the 4 lanes (lane&3) sharing each token row.
    int* sIdx = reinterpret_cast<int*>(sm + OFF_IDX);
#pragma unroll
    for (int slot = 0; slot < 2; slot++) {
        float bv = best[slot], sv = sec[slot];
        int bi = bidx[slot];
#pragma unroll
        for (int off = 1; off <= 2; off <<= 1) {
            float ob = __shfl_xor_sync(0xffffffffu, bv, off);
            float os = __shfl_xor_sync(0xffffffffu, sv, off);
            int   oi = __shfl_xor_sync(0xffffffffu, bi, off);
            sv = fmaxf(fmaxf(sv, os), fminf(bv, ob));
            bool t = (ob > bv) || (ob == bv && oi < bi);  // tie -> smaller idx
            bv = t ? ob : bv;
            bi = t ? oi : bi;
        }
        if ((lane & 3) == 0) {
            int m = warp * 16 + (lane >> 2) + slot * 8;
            sIdx[m] = bi;
            g_flag[n0 + m] = (bv - sv < TAU) ? 1 : 0;
            outidx[n0 + m] = (float)bi;
        }
    }
    __syncthreads();

    // Gather winning codebook rows; coalesced over tokens per dim.
    float* obase = out + (size_t)b * D * TLEN + t0;
    for (int i = tid; i < MTOK * D; i += THREADS) {
        int d = i >> 7, mm = i & 127;
        obase[(size_t)d * TLEN + mm] = cb[sIdx[mm] * D + d];
    }
}

// ============================ exact refine ==================================
// One warp per flagged token; exact fp32 fmaf chain (matched reference R1/R2).
__global__ void __launch_bounds__(256) vq_refine(const float* __restrict__ xin,
                                                 const float* __restrict__ cb,
                                                 float* __restrict__ out,
                                                 float* __restrict__ outidx,
                                                 int Ntok) {
    __shared__ float sx[8][D];
    const int wid = threadIdx.x >> 5, lid = threadIdx.x & 31;
    const int n = blockIdx.x * 8 + wid;
    if (n >= Ntok) return;
    if (g_flag[n] == 0) return;

    const int b = n / TLEN, t = n % TLEN;
    const float* xp = xin + (size_t)b * D * TLEN + t;
    sx[wid][lid]      = xp[(size_t)lid * TLEN];
    sx[wid][lid + 32] = xp[(size_t)(lid + 32) * TLEN];
    __syncwarp();

    float best = -3.4e38f;
    int   bi = 0;
    for (int kk = 0; kk < KCB / 32; kk++) {
        int k = kk * 32 + lid;
        const float4* row = reinterpret_cast<const float4*>(cb + (size_t)k * D);
        float dot = 0.0f;
#pragma unroll
        for (int q = 0; q < 16; q++) {
            float4 e = row[q];
            dot = fmaf(sx[wid][4 * q + 0], e.x, dot);
            dot = fmaf(sx[wid][4 * q + 1], e.y, dot);
            dot = fmaf(sx[wid][4 * q + 2], e.z, dot);
            dot = fmaf(sx[wid][4 * q + 3], e.w, dot);
        }
        float s = dot - g_h[k];
        if (s > best) { best = s; bi = k; }
    }
#pragma unroll
    for (int off = 16; off; off >>= 1) {   // tie -> smaller index
        float ov = __shfl_xor_sync(0xffffffffu, best, off);
        int   oi = __shfl_xor_sync(0xffffffffu, bi, off);
        if (ov > best || (ov == best && oi < bi)) { best = ov; bi = oi; }
    }
    bi = __shfl_sync(0xffffffffu, bi, 0);

    float* op = out + (size_t)b * D * TLEN + t;
    op[(size_t)lid * TLEN]        = cb[bi * D + lid];
    op[(size_t)(lid + 32) * TLEN] = cb[bi * D + lid + 32];
    if (lid == 0) outidx[n] = (float)bi;
}

// ============================ launch ========================================
extern "C" void kernel_launch(void* const* d_in, const int* in_sizes, int n_in,
                              void* d_out, int out_size) {
    const float* x  = (const float*)d_in[0];   // (16, 64, 8192)
    const float* cb = (const float*)d_in[1];   // (1024, 64)
    float* out = (float*)d_out;

    const int N = in_sizes[0] / D;
    float* oidx = out + (size_t)N * D;

    cudaFuncSetAttribute(vq_mma, cudaFuncAttributeMaxDynamicSharedMemorySize,
                         SMEM_TOTAL);

    vq_prep<<<32, 256>>>(cb);
    vq_mma<<<N / MTOK, THREADS, SMEM_TOTAL>>>(x, cb, out, oidx);
    vq_refine<<<N / 8, 256>>>(x, cb, out, oidx, N);
}

// round 8
// speedup vs baseline: 2.0811x; 1.0988x over previous
#include <cuda_runtime.h>
#include <cuda_fp16.h>
#include <cstdint>

#define D       64
#define KCB     1024
#define TLEN    8192
#define MTOK    128       // tokens per CTA
#define THREADS 256       // 8 warps, 16 tokens per warp
#define CHUNK   256       // codes per chunk
#define NCHUNK  4
#define TAU     0.09f
#define NTOKMAX 131072

// ---- vq_mma dynamic smem layout (bytes) ----
#define OFF_XH   0                 // 128 tokens x 128B rows (fp16), SW128
#define OFF_B    16384             // 2 bufs x 32KB (256 codes x 128B fp16)
#define OFF_H    81920             // float[1024]
#define OFF_IDX  86016             // int[128]
#define SMEM_TOTAL 86528

// ---- vq_refine2 dynamic smem layout (floats/bytes) ----
#define RSTRIDE  268               // padded row stride (floats): <=2-way STS conflicts
#define ROFF_E   0                 // float[64*268]  (68608 B)
#define ROFF_H   68608             // float[256]
#define ROFF_X   69632             // float[8][64]
#define RSMEM_TOTAL 71680
#define RBLKS    256

// ---- global scratch (no allocs allowed in kernel_launch) ----
__device__ __align__(16) __half g_cbH[KCB * D];   // fp16 codebook [k][d]
__device__ float g_h[KCB];                         // 0.5*||e_k||^2 (fp32)
__device__ int   g_nflag;                          // compacted flag count
__device__ int   g_flagged[NTOKMAX];               // flagged token ids

// ============================ PTX helpers ===================================
__device__ __forceinline__ uint32_t smem_u32(const void* p) {
    uint32_t a;
    asm("{ .reg .u64 t; cvta.to.shared.u64 t, %1; cvt.u32.u64 %0, t; }"
        : "=r"(a) : "l"(p));
    return a;
}
__device__ __forceinline__ void ldsm_x4(uint32_t r[4], uint32_t addr) {
    asm volatile("ldmatrix.sync.aligned.m8n8.x4.shared.b16 {%0,%1,%2,%3}, [%4];"
                 : "=r"(r[0]), "=r"(r[1]), "=r"(r[2]), "=r"(r[3]) : "r"(addr));
}
__device__ __forceinline__ void mma_f16(float c[4], const uint32_t a[4],
                                        uint32_t b0, uint32_t b1) {
    asm volatile(
        "mma.sync.aligned.m16n8k16.row.col.f32.f16.f16.f32 "
        "{%0,%1,%2,%3}, {%4,%5,%6,%7}, {%8,%9}, {%0,%1,%2,%3};"
        : "+f"(c[0]), "+f"(c[1]), "+f"(c[2]), "+f"(c[3])
        : "r"(a[0]), "r"(a[1]), "r"(a[2]), "r"(a[3]), "r"(b0), "r"(b1));
}
__device__ __forceinline__ void cp16(uint32_t dst, const void* src) {
    asm volatile("cp.async.ca.shared.global [%0], [%1], 16;"
                 :: "r"(dst), "l"(src) : "memory");
}
__device__ __forceinline__ void cp_commit() {
    asm volatile("cp.async.commit_group;" ::: "memory");
}
template <int N> __device__ __forceinline__ void cp_wait() {
    asm volatile("cp.async.wait_group %0;" :: "n"(N) : "memory");
}
__device__ __forceinline__ uint32_t sw128(uint32_t off) {
    return off ^ ((off >> 3) & 0x70);
}

// ============================ prep ==========================================
// Warp per 4 codes: coalesced row loads, fp16 convert, shfl-reduced h[k].
// Also resets the flag-compaction counter for this launch.
__global__ void __launch_bounds__(256) vq_prep(const float* __restrict__ cb) {
    if (blockIdx.x == 0 && threadIdx.x == 0) g_nflag = 0;
    const int lane = threadIdx.x & 31, w = threadIdx.x >> 5;
    const int wglobal = blockIdx.x * 8 + w;        // 256 warps
#pragma unroll
    for (int i = 0; i < 4; i++) {
        int k = wglobal * 4 + i;                   // 1024 codes
        float f0 = cb[k * D + lane];
        float f1 = cb[k * D + lane + 32];
        g_cbH[k * D + lane]      = __float2half(f0);
        g_cbH[k * D + lane + 32] = __float2half(f1);
        float s = fmaf(f0, f0, f1 * f1);
#pragma unroll
        for (int off = 16; off; off >>= 1)
            s += __shfl_xor_sync(0xffffffffu, s, off);
        if (lane == 0) g_h[k] = 0.5f * s;
    }
}

// ============================ main (fp16 single-pass) =======================
__device__ __forceinline__ void issueB(uint32_t smbase, int buf, int chunk, int tid) {
    uint32_t dst = smbase + OFF_B + buf * 32768;
    const char* src = reinterpret_cast<const char*>(g_cbH) + (size_t)chunk * CHUNK * D * 2;
#pragma unroll
    for (int i = tid; i < 2048; i += THREADS) {
        int code = i >> 3, q = i & 7;
        uint32_t sw = sw128((uint32_t)(code * 128 + q * 16));
        cp16(dst + sw, src + i * 16);
    }
}

__device__ __forceinline__ void upd(float& b, float& s, int& bi, float v, int k) {
    s = fmaxf(s, fminf(v, b));      // running second-best
    if (v > b) { b = v; bi = k; }   // strict > keeps first occurrence
}

__global__ void __launch_bounds__(THREADS, 1)
vq_mma(const float* __restrict__ xin, const float* __restrict__ cb,
       float* __restrict__ out, float* __restrict__ outidx) {
    extern __shared__ __align__(1024) char sm[];
    const uint32_t smbase = smem_u32(sm);
    const int tid  = threadIdx.x;
    const int lane = tid & 31, warp = tid >> 5;

    const int n0 = blockIdx.x * MTOK;
    const int b  = n0 >> 13;            // / TLEN
    const int t0 = n0 & (TLEN - 1);

    // Kick off codebook chunks 0,1 so they overlap X staging.
    issueB(smbase, 0, 0, tid); cp_commit();
    issueB(smbase, 1, 1, tid); cp_commit();

    // Stage X as fp16, SW128 rows of 128B (row = token).
    const float* xbase = xin + (size_t)b * D * TLEN + t0;
    for (int i = tid; i < MTOK * D; i += THREADS) {
        int d = i >> 7, m = i & 127;    // coalesced over m
        float v = xbase[(size_t)d * TLEN + m];
        uint32_t sw = sw128((uint32_t)(m * 128 + d * 2));
        *reinterpret_cast<__half*>(sm + OFF_XH + sw) = __float2half(v);
    }
    float* sH = reinterpret_cast<float*>(sm + OFF_H);
    for (int i = tid; i < KCB; i += THREADS) sH[i] = g_h[i];
    __syncthreads();    // X + h visible to all warps

    // A fragments (held in registers for the whole kernel).
    uint32_t aX[4][4];
    {
        int arow = warp * 16 + (lane & 15);
        int adim = (lane >> 4) * 16;            // byte offset of 8-dim half
#pragma unroll
        for (int s = 0; s < 4; s++) {
            uint32_t sw = sw128((uint32_t)(arow * 128 + s * 32 + adim));
            ldsm_x4(aX[s], smbase + OFF_XH + sw);
        }
    }

    // B-fragment addressing (16 codes x 16 dims per ldmatrix.x4).
    const uint32_t browoff = (uint32_t)(((lane & 7) + ((lane >> 4) << 3)) * 128);
    const uint32_t bxor = (uint32_t)((lane & 7) << 4);
    uint32_t bdim[4];
#pragma unroll
    for (int s = 0; s < 4; s++)
        bdim[s] = ((uint32_t)(s * 32 + ((lane >> 3) & 1) * 16)) ^ bxor;

    float best[2] = {-3.4e38f, -3.4e38f}, sec[2] = {-3.4e38f, -3.4e38f};
    int   bidx[2] = {0, 0};
    const int hcol = (lane & 3) * 2;

    for (int c = 0; c < NCHUNK; c++) {
        if (c == NCHUNK - 1) cp_wait<0>(); else cp_wait<1>();
        __syncthreads();                 // buf (c&1) ready for everyone
        const uint32_t buf = smbase + OFF_B + (c & 1) * 32768;

#pragma unroll 4
        for (int ns = 0; ns < CHUNK / 16; ns++) {
            const uint32_t ro = browoff + (uint32_t)(ns * 16 * 128);
            float a0[4] = {0, 0, 0, 0};          // cols kb..kb+7  (rows r, r+8)
            float a1[4] = {0, 0, 0, 0};          // cols kb+8..kb+15
#pragma unroll
            for (int s = 0; s < 4; s++) {
                uint32_t rh[4];
                ldsm_x4(rh, buf + ro + bdim[s]);
                mma_f16(a0, aX[s], rh[0], rh[1]);
                mma_f16(a1, aX[s], rh[2], rh[3]);
            }
            const int kb = c * CHUNK + ns * 16;
            float2 h0 = *reinterpret_cast<const float2*>(&sH[kb + hcol]);
            float2 h1 = *reinterpret_cast<const float2*>(&sH[kb + 8 + hcol]);
            // slot 0 = token row r (c0,c1); slot 1 = row r+8 (c2,c3).
            upd(best[0], sec[0], bidx[0], a0[0] - h0.x, kb + hcol);
            upd(best[0], sec[0], bidx[0], a0[1] - h0.y, kb + hcol + 1);
            upd(best[0], sec[0], bidx[0], a1[0] - h1.x, kb + 8 + hcol);
            upd(best[0], sec[0], bidx[0], a1[1] - h1.y, kb + 8 + hcol + 1);
            upd(best[1], sec[1], bidx[1], a0[2] - h0.x, kb + hcol);
            upd(best[1], sec[1], bidx[1], a0[3] - h0.y, kb + hcol + 1);
            upd(best[1], sec[1], bidx[1], a1[2] - h1.x, kb + 8 + hcol);
            upd(best[1], sec[1], bidx[1], a1[3] - h1.y, kb + 8 + hcol + 1);
        }
        __syncthreads();                 // everyone done reading buf (c&1)
        if (c + 2 < NCHUNK) { issueB(smbase, c & 1, c + 2, tid); cp_commit(); }
    }

    // Reduce across the 4 lanes (lane&3) sharing each token row.
    int* sIdx = reinterpret_cast<int*>(sm + OFF_IDX);
#pragma unroll
    for (int slot = 0; slot < 2; slot++) {
        float bv = best[slot], sv = sec[slot];
        int bi = bidx[slot];
#pragma unroll
        for (int off = 1; off <= 2; off <<= 1) {
            float ob = __shfl_xor_sync(0xffffffffu, bv, off);
            float os = __shfl_xor_sync(0xffffffffu, sv, off);
            int   oi = __shfl_xor_sync(0xffffffffu, bi, off);
            sv = fmaxf(fmaxf(sv, os), fminf(bv, ob));
            bool t = (ob > bv) || (ob == bv && oi < bi);  // tie -> smaller idx
            bv = t ? ob : bv;
            bi = t ? oi : bi;
        }
        if ((lane & 3) == 0) {
            int m = warp * 16 + (lane >> 2) + slot * 8;
            sIdx[m] = bi;
            outidx[n0 + m] = (float)bi;
            if (bv - sv < TAU) {               // margin too small: exact recheck
                int p = atomicAdd(&g_nflag, 1);
                g_flagged[p] = n0 + m;
            }
        }
    }
    __syncthreads();

    // Gather winning codebook rows; coalesced over tokens per dim.
    float* obase = out + (size_t)b * D * TLEN + t0;
    for (int i = tid; i < MTOK * D; i += THREADS) {
        int d = i >> 7, mm = i & 127;
        obase[(size_t)d * TLEN + mm] = cb[sIdx[mm] * D + d];
    }
}

// ============================ exact refine (tiled) ==========================
// Grid-stride blocks of 8 warps; each block iteration serves 8 flagged tokens
// against smem-staged fp32 codebook tiles (amortizes L2 traffic 8x and keeps
// reads conflict-free). Scores use the exact fp32 d-ascending fmaf chain.
__global__ void __launch_bounds__(256) vq_refine2(const float* __restrict__ xin,
                                                  const float* __restrict__ cb,
                                                  float* __restrict__ out,
                                                  float* __restrict__ outidx) {
    extern __shared__ __align__(16) char rsm[];
    float* sE = reinterpret_cast<float*>(rsm + ROFF_E);   // [64][RSTRIDE]
    float* sh = reinterpret_cast<float*>(rsm + ROFF_H);   // [256]
    float* sx = reinterpret_cast<float*>(rsm + ROFF_X);   // [8][64]

    const int tid = threadIdx.x, lane = tid & 31, w = tid >> 5;
    const int count = g_nflag;

    for (int base = blockIdx.x * 8; base < count; base += gridDim.x * 8) {
        int mytok = (base + w < count) ? g_flagged[base + w] : -1;
        if (mytok >= 0) {
            int bq = mytok >> 13, tq = mytok & (TLEN - 1);
            const float* xp = xin + (size_t)bq * D * TLEN + tq;
            sx[w * D + lane]      = xp[(size_t)lane * TLEN];
            sx[w * D + lane + 32] = xp[(size_t)(lane + 32) * TLEN];
        }
        __syncwarp();

        float best = -3.4e38f;
        int   bi = 0;
        for (int tile = 0; tile < 4; tile++) {
            __syncthreads();   // previous tile fully consumed / sx ready
            // Stage codebook tile transposed: sE[d][code], 256 codes.
            for (int i = tid; i < 256 * 16; i += 256) {
                int code = i >> 4, q = i & 15;
                float4 v = reinterpret_cast<const float4*>(
                    cb + (size_t)(tile * 256 + code) * D)[q];
                float* dst = &sE[(4 * q) * RSTRIDE + code];
                dst[0]           = v.x;
                dst[RSTRIDE]     = v.y;
                dst[2 * RSTRIDE] = v.z;
                dst[3 * RSTRIDE] = v.w;
            }
            for (int i = tid; i < 256; i += 256) sh[i] = g_h[tile * 256 + i];
            __syncthreads();

            if (mytok >= 0) {
                // Lane handles codes 4*lane..+3 and 128+4*lane..+3 (ascending).
                float acc[8] = {0, 0, 0, 0, 0, 0, 0, 0};
                const float4* xr = reinterpret_cast<const float4*>(&sx[w * D]);
#pragma unroll
                for (int q = 0; q < 16; q++) {
                    float4 xx = xr[q];
                    float xv[4] = {xx.x, xx.y, xx.z, xx.w};
#pragma unroll
                    for (int dd = 0; dd < 4; dd++) {
                        const float* ep = &sE[(4 * q + dd) * RSTRIDE];
                        float4 e0 = *reinterpret_cast<const float4*>(&ep[4 * lane]);
                        float4 e1 = *reinterpret_cast<const float4*>(&ep[128 + 4 * lane]);
                        acc[0] = fmaf(xv[dd], e0.x, acc[0]);
                        acc[1] = fmaf(xv[dd], e0.y, acc[1]);
                        acc[2] = fmaf(xv[dd], e0.z, acc[2]);
                        acc[3] = fmaf(xv[dd], e0.w, acc[3]);
                        acc[4] = fmaf(xv[dd], e1.x, acc[4]);
                        acc[5] = fmaf(xv[dd], e1.y, acc[5]);
                        acc[6] = fmaf(xv[dd], e1.z, acc[6]);
                        acc[7] = fmaf(xv[dd], e1.w, acc[7]);
                    }
                }
#pragma unroll
                for (int j = 0; j < 4; j++) {
                    int k0 = tile * 256 + 4 * lane + j;
                    float s0 = acc[j] - sh[4 * lane + j];
                    if (s0 > best) { best = s0; bi = k0; }
                }
#pragma unroll
                for (int j = 0; j < 4; j++) {
                    int k1 = tile * 256 + 128 + 4 * lane + j;
                    float s1 = acc[4 + j] - sh[128 + 4 * lane + j];
                    if (s1 > best) { best = s1; bi = k1; }
                }
            }
        }

        if (mytok >= 0) {
#pragma unroll
            for (int off = 16; off; off >>= 1) {   // tie -> smaller index
                float ov = __shfl_xor_sync(0xffffffffu, best, off);
                int   oi = __shfl_xor_sync(0xffffffffu, bi, off);
                if (ov > best || (ov == best && oi < bi)) { best = ov; bi = oi; }
            }
            bi = __shfl_sync(0xffffffffu, bi, 0);

            int bq = mytok >> 13, tq = mytok & (TLEN - 1);
            float* op = out + (size_t)bq * D * TLEN + tq;
            op[(size_t)lane * TLEN]        = cb[bi * D + lane];
            op[(size_t)(lane + 32) * TLEN] = cb[bi * D + lane + 32];
            if (lane == 0) outidx[mytok] = (float)bi;
        }
        __syncthreads();   // all writes done before next iteration reloads sE
    }
}

// ============================ launch ========================================
extern "C" void kernel_launch(void* const* d_in, const int* in_sizes, int n_in,
                              void* d_out, int out_size) {
    const float* x  = (const float*)d_in[0];   // (16, 64, 8192)
    const float* cb = (const float*)d_in[1];   // (1024, 64)
    float* out = (float*)d_out;

    const int N = in_sizes[0] / D;
    float* oidx = out + (size_t)N * D;

    cudaFuncSetAttribute(vq_mma, cudaFuncAttributeMaxDynamicSharedMemorySize,
                         SMEM_TOTAL);
    cudaFuncSetAttribute(vq_refine2, cudaFuncAttributeMaxDynamicSharedMemorySize,
                         RSMEM_TOTAL);

    vq_prep<<<32, 256>>>(cb);
    vq_mma<<<N / MTOK, THREADS, SMEM_TOTAL>>>(x, cb, out, oidx);
    vq_refine2<<<RBLKS, 256, RSMEM_TOTAL>>>(x, cb, out, oidx);
}